// round 1
// baseline (speedup 1.0000x reference)
#include <cuda_runtime.h>

#define HH 256
#define WW 256
#define NPIX 65536

// ---------------- scratch (device globals; no allocation) ----------------
__device__ float g_tilt[3 * NPIX];
__device__ float g_h1[(size_t)NPIX * 200];
__device__ float g_h2[(size_t)NPIX * 200];
__device__ float g_coef[(size_t)NPIX * 100];
__device__ float g_A[40 * NPIX];    // plane p = img*10 + j, img 0..2 = tilt RGB, img 3 = denominator
__device__ float g_Bmu[30 * NPIX];  // plane p = img*10 + m, img 0..2 = tilt RGB
__device__ float g_denmu;

// ---------------- denominator mu constant: sum_m (sum_t mu[t,m])^2 ----------------
__global__ void k_denmu(const float* __restrict__ mu) {
    int tid = threadIdx.x;
    __shared__ float S[10];
    if (tid < 10) {
        float s = 0.f;
        for (int t = 0; t < 65; t++) s += mu[t * 10 + tid];
        S[tid] = s * s;
    }
    __syncthreads();
    if (tid == 0) {
        float d = 0.f;
        for (int m = 0; m < 10; m++) d += S[m];
        g_denmu = d;
    }
}

// ---------------- bilinear grid sample (border padding, align_corners=False) ----------------
__global__ void k_gridsample(const float* __restrict__ img, const float* __restrict__ zern) {
    int p = blockIdx.x * blockDim.x + threadIdx.x;
    if (p >= NPIX) return;
    int y = p >> 8, x = p & 255;
    float px = zern[p * 35 + 0], py = zern[p * 35 + 1];
    float fx = 2.0f * ((float)x + px) / 255.0f - 1.0f;
    float fy = 2.0f * ((float)y + py) / 255.0f - 1.0f;
    float ix = ((fx + 1.0f) * 256.0f - 1.0f) * 0.5f;
    float iy = ((fy + 1.0f) * 256.0f - 1.0f) * 0.5f;
    ix = fminf(fmaxf(ix, 0.f), 255.f);
    iy = fminf(fmaxf(iy, 0.f), 255.f);
    float x0f = floorf(ix), y0f = floorf(iy);
    float wx = ix - x0f, wy = iy - y0f;
    int x0 = (int)x0f, y0 = (int)y0f;
    int x1 = min(x0 + 1, 255), y1 = min(y0 + 1, 255);
#pragma unroll
    for (int c = 0; c < 3; c++) {
        const float* im = img + c * NPIX;
        float g00 = im[y0 * 256 + x0], g01 = im[y0 * 256 + x1];
        float g10 = im[y1 * 256 + x0], g11 = im[y1 * 256 + x1];
        float top = g00 * (1.f - wx) + g01 * wx;
        float bot = g10 * (1.f - wx) + g11 * wx;
        g_tilt[c * NPIX + p] = top * (1.f - wy) + bot * wy;
    }
}

// ---------------- generic tiled SGEMM: C[m,n] = act( sum_k A[m, aoff+k] * Wt[n,k] + bias[n] ) ----------------
// BM=BN=64, BK=8, 256 threads, 4x4 per thread. M is fixed at 65536 (grid.y = 1024).
__global__ __launch_bounds__(256) void k_gemm(const float* __restrict__ A, int lda, int aoff,
                                              const float* __restrict__ Wt, const float* __restrict__ bias,
                                              float* __restrict__ C, int N, int K, int act) {
    __shared__ __align__(16) float As[8 * 68];
    __shared__ __align__(16) float Bs[8 * 68];
    int m0 = blockIdx.y * 64, n0 = blockIdx.x * 64;
    int tid = threadIdx.x;
    int tx = tid & 15, ty = tid >> 4;
    float acc[4][4] = {};
    for (int k0 = 0; k0 < K; k0 += 8) {
#pragma unroll
        for (int r = 0; r < 2; r++) {
            int li = tid + r * 256;
            int kk = li & 7, mm = li >> 3;
            float av = 0.f;
            if (k0 + kk < K) av = A[(size_t)(m0 + mm) * lda + aoff + k0 + kk];
            As[kk * 68 + mm] = av;
            float bv = 0.f;
            if (k0 + kk < K && n0 + mm < N) bv = Wt[(n0 + mm) * K + k0 + kk];
            Bs[kk * 68 + mm] = bv;
        }
        __syncthreads();
#pragma unroll
        for (int kk = 0; kk < 8; kk++) {
            float4 a = *(const float4*)&As[kk * 68 + ty * 4];
            float4 b = *(const float4*)&Bs[kk * 68 + tx * 4];
            float ar[4] = {a.x, a.y, a.z, a.w};
            float br[4] = {b.x, b.y, b.z, b.w};
#pragma unroll
            for (int i = 0; i < 4; i++)
#pragma unroll
                for (int j = 0; j < 4; j++) acc[i][j] += ar[i] * br[j];
        }
        __syncthreads();
    }
#pragma unroll
    for (int i = 0; i < 4; i++) {
        int m = m0 + ty * 4 + i;
#pragma unroll
        for (int j = 0; j < 4; j++) {
            int n = n0 + tx * 4 + j;
            if (n < N) {
                float v = acc[i][j] + bias[n];
                if (act) v = v > 0.f ? v : 0.01f * v;
                C[(size_t)m * N + n] = v;
            }
        }
    }
}

// ---------------- vertical pass (basis_left x coef contraction, shared across 4 images) ----------------
// One block per column w. Whole column of coef (256 x 100) staged transposed [c][h] in smem.
// A_j^img(h) = sum_t tilt_img(r) * s_j(r,t),  s_j = sum_i L[t,i] * coef[r, i*10+j],  r = reflect(h+t-32)
__global__ void k_vert(const float* __restrict__ basis_left) {
    extern __shared__ float sm[];
    float* coefS = sm;               // 100 * 257
    float* tiltS = sm + 100 * 257;   // 3 * 257
    float* Lsm = sm + 103 * 257;     // 650
    int w = blockIdx.x, tid = threadIdx.x;
    for (int i = tid; i < 650; i += 256) Lsm[i] = basis_left[i];
    for (int li = tid; li < 6400; li += 256) {  // 6400 float4 = 256 rows * 100 floats
        int hh = li / 25, q = li % 25;
        float4 v = *(const float4*)&g_coef[(size_t)(hh * 256 + w) * 100 + q * 4];
        int c = q * 4;
        coefS[(c + 0) * 257 + hh] = v.x;
        coefS[(c + 1) * 257 + hh] = v.y;
        coefS[(c + 2) * 257 + hh] = v.z;
        coefS[(c + 3) * 257 + hh] = v.w;
    }
    for (int li = tid; li < 768; li += 256) {
        int k = li >> 8, hh = li & 255;
        tiltS[k * 257 + hh] = g_tilt[k * NPIX + hh * 256 + w];
    }
    __syncthreads();
    int h = tid;
    float acc[40];
#pragma unroll
    for (int q = 0; q < 40; q++) acc[q] = 0.f;
    for (int t = 0; t < 65; t++) {
        int r = h + t - 32;
        r = (r < 0) ? -r : ((r > 255) ? 510 - r : r);
        float s[10];
#pragma unroll
        for (int j = 0; j < 10; j++) s[j] = 0.f;
#pragma unroll
        for (int i = 0; i < 10; i++) {
            float Li = Lsm[t * 10 + i];
#pragma unroll
            for (int j = 0; j < 10; j++) s[j] += Li * coefS[(i * 10 + j) * 257 + r];
        }
        float t0 = tiltS[r], t1 = tiltS[257 + r], t2 = tiltS[514 + r];
#pragma unroll
        for (int j = 0; j < 10; j++) {
            acc[j] += t0 * s[j];
            acc[10 + j] += t1 * s[j];
            acc[20 + j] += t2 * s[j];
            acc[30 + j] += s[j];  // denominator image = 1
        }
    }
#pragma unroll
    for (int p = 0; p < 40; p++) g_A[p * NPIX + h * 256 + w] = acc[p];
}

// ---------------- vertical mu pass: Bmu_m^img = V_mu_m[tilt_img] ----------------
__global__ void k_vmu(const float* __restrict__ mu) {
    __shared__ float tiltS[3 * 257];
    __shared__ float Msm[650];
    int w = blockIdx.x, tid = threadIdx.x;
    for (int i = tid; i < 650; i += 256) Msm[i] = mu[i];
    for (int li = tid; li < 768; li += 256) {
        int k = li >> 8, hh = li & 255;
        tiltS[k * 257 + hh] = g_tilt[k * NPIX + hh * 256 + w];
    }
    __syncthreads();
    int h = tid;
    float acc[30];
#pragma unroll
    for (int q = 0; q < 30; q++) acc[q] = 0.f;
    for (int t = 0; t < 65; t++) {
        int r = h + t - 32;
        r = (r < 0) ? -r : ((r > 255) ? 510 - r : r);
        float t0 = tiltS[r], t1 = tiltS[257 + r], t2 = tiltS[514 + r];
#pragma unroll
        for (int m = 0; m < 10; m++) {
            float mv = Msm[t * 10 + m];
            acc[m] += mv * t0;
            acc[10 + m] += mv * t1;
            acc[20 + m] += mv * t2;
        }
    }
#pragma unroll
    for (int p = 0; p < 30; p++) g_Bmu[p * NPIX + h * 256 + w] = acc[p];
}

// ---------------- horizontal pass + channel sum + divide ----------------
// block = 128 outputs on one row; stages a [w0-32, w0+159] window of all 70 planes in smem.
__global__ void k_horiz(const float* __restrict__ basis_right, const float* __restrict__ mu,
                        float* __restrict__ out) {
    extern __shared__ float sm[];
    float* P = sm;                 // 70 * 193
    float* Rsm = sm + 70 * 193;    // 650
    float* Msm = Rsm + 650;        // 650
    int h = blockIdx.y;
    int w0 = blockIdx.x * 128;
    int tid = threadIdx.x;  // 128
    for (int i = tid; i < 650; i += 128) {
        Rsm[i] = basis_right[i];
        Msm[i] = mu[i];
    }
    int base = w0 - 32;
    if (base < 0) base = 0;
    int wend = w0 + 127 + 32;
    if (wend > 255) wend = 255;
    int width = wend - base + 1;
    for (int p = 0; p < 70; p++) {
        const float* src = (p < 40) ? (g_A + p * NPIX + h * 256) : (g_Bmu + (p - 40) * NPIX + h * 256);
        for (int c = tid; c < width; c += 128) P[p * 193 + c] = src[base + c];
    }
    __syncthreads();
    int w = w0 + tid;
    float n0a = 0.f, n1a = 0.f, n2a = 0.f, den = 0.f;
    for (int s = 0; s < 65; s++) {
        int wp = w + s - 32;
        wp = (wp < 0) ? -wp : ((wp > 255) ? 510 - wp : wp);
        int c = wp - base;
#pragma unroll
        for (int j = 0; j < 10; j++) {
            float Rv = Rsm[s * 10 + j];
            n0a += Rv * P[j * 193 + c];
            n1a += Rv * P[(10 + j) * 193 + c];
            n2a += Rv * P[(20 + j) * 193 + c];
            den += Rv * P[(30 + j) * 193 + c];
        }
#pragma unroll
        for (int m = 0; m < 10; m++) {
            float Mv = Msm[s * 10 + m];
            n0a += Mv * P[(40 + m) * 193 + c];
            n1a += Mv * P[(50 + m) * 193 + c];
            n2a += Mv * P[(60 + m) * 193 + c];
        }
    }
    den += g_denmu;
    out[0 * NPIX + h * 256 + w] = n0a / den;
    out[1 * NPIX + h * 256 + w] = n1a / den;
    out[2 * NPIX + h * 256 + w] = n2a / den;
}

// ---------------- launcher ----------------
extern "C" void kernel_launch(void* const* d_in, const int* in_sizes, int n_in,
                              void* d_out, int out_size) {
    const float* img  = (const float*)d_in[0];
    const float* zern = (const float*)d_in[1];
    const float* fc1w = (const float*)d_in[2];
    const float* fc1b = (const float*)d_in[3];
    const float* fc2w = (const float*)d_in[4];
    const float* fc2b = (const float*)d_in[5];
    const float* fc3w = (const float*)d_in[6];
    const float* fc3b = (const float*)d_in[7];
    const float* bl   = (const float*)d_in[8];
    const float* br   = (const float*)d_in[9];
    const float* mu   = (const float*)d_in[10];
    float* out = (float*)d_out;

    cudaFuncSetAttribute(k_vert, cudaFuncAttributeMaxDynamicSharedMemorySize, 108484);
    cudaFuncSetAttribute(k_horiz, cudaFuncAttributeMaxDynamicSharedMemorySize, 59240);

    float *h1, *h2, *coef;
    cudaGetSymbolAddress((void**)&h1, g_h1);
    cudaGetSymbolAddress((void**)&h2, g_h2);
    cudaGetSymbolAddress((void**)&coef, g_coef);

    k_denmu<<<1, 64>>>(mu);
    k_gridsample<<<256, 256>>>(img, zern);
    k_gemm<<<dim3(4, 1024), 256>>>(zern, 35, 2, fc1w, fc1b, h1, 200, 33, 1);
    k_gemm<<<dim3(4, 1024), 256>>>(h1, 200, 0, fc2w, fc2b, h2, 200, 200, 1);
    k_gemm<<<dim3(2, 1024), 256>>>(h2, 200, 0, fc3w, fc3b, coef, 100, 200, 0);
    k_vert<<<256, 256, 108484>>>(bl);
    k_vmu<<<256, 256>>>(mu);
    k_horiz<<<dim3(2, 256), 128, 59240>>>(br, mu, out);
}

// round 3
// speedup vs baseline: 1.5653x; 1.5653x over previous
#include <cuda_runtime.h>
#include <cuda_bf16.h>
#include <cstdint>

#define NPIX 65536

// ---------------- scratch (device globals; no allocation) ----------------
__device__ float g_tilt[3 * NPIX];
__device__ float g_h1[(size_t)NPIX * 200];
__device__ float g_h2[(size_t)NPIX * 200];
__device__ float g_coef[(size_t)NPIX * 100];
__device__ float g_A[40 * NPIX];
__device__ float g_Bmu[30 * NPIX];
__device__ float g_denmu;

// ---------------- warp-mma helpers ----------------
__device__ __forceinline__ void mma_bf16(float* c, uint32_t a0, uint32_t a1, uint32_t a2,
                                         uint32_t a3, uint32_t b0, uint32_t b1) {
    asm volatile(
        "mma.sync.aligned.m16n8k16.row.col.f32.bf16.bf16.f32 "
        "{%0,%1,%2,%3}, {%4,%5,%6,%7}, {%8,%9}, {%0,%1,%2,%3};"
        : "+f"(c[0]), "+f"(c[1]), "+f"(c[2]), "+f"(c[3])
        : "r"(a0), "r"(a1), "r"(a2), "r"(a3), "r"(b0), "r"(b1));
}
__device__ __forceinline__ uint32_t pack_bf16x2(float a, float b) {
    __nv_bfloat162 t;
    t.x = __float2bfloat16(a);
    t.y = __float2bfloat16(b);
    return *reinterpret_cast<uint32_t*>(&t);
}

// ================= split-bf16 warp-mma MLP layer =================
// C[m, 0..NOUT) = act( sum_k A[m, AOFF+k] * W[n, k] + bias[n] ), m in [0, 65536)
// W [NOUT x K] fp32 row-major. 3-pass split bf16: hi*hi + hi*lo + lo*hi.
template <int NOUT, int K, int LDA, int AOFF, int ACT>
__global__ __launch_bounds__(256, 1) void k_mlp(const float* __restrict__ A,
                                                const float* __restrict__ W,
                                                const float* __restrict__ bias,
                                                float* __restrict__ C) {
    constexpr int NP = (NOUT + 7) & ~7;     // padded N
    constexpr int NT = NP / 8;              // n-tiles of 8
    constexpr int KC = (K + 15) / 16;       // k-chunks of 16
    constexpr int KP = KC * 16;
    constexpr int KS = KP + 2;              // smem k-stride (elems); KS/2 words odd
    constexpr bool VEC = (LDA % 2 == 0) && (AOFF % 2 == 0);

    extern __shared__ char smraw[];
    __nv_bfloat16* sh = reinterpret_cast<__nv_bfloat16*>(smraw);
    __nv_bfloat16* sl = sh + NP * KS;
    float* bias_s = reinterpret_cast<float*>(sl + NP * KS);

    int tid = threadIdx.x;
    int lane = tid & 31, warp = tid >> 5;

    // ---- stage weights hi/lo + bias (once per CTA) ----
    for (int idx = tid; idx < NP * KP; idx += 256) {
        int n = idx / KP, k = idx % KP;
        float v = (n < NOUT && k < K) ? W[n * K + k] : 0.0f;
        __nv_bfloat16 h = __float2bfloat16(v);
        float lo = v - __bfloat162float(h);
        sh[n * KS + k] = h;
        sl[n * KS + k] = __float2bfloat16(lo);
    }
    for (int i = tid; i < NP; i += 256) bias_s[i] = (i < NOUT) ? bias[i] : 0.0f;
    __syncthreads();

    const int k0 = (lane & 3) * 2;
    const int nrow = lane >> 2;

    for (int tile = blockIdx.x; tile < 512; tile += gridDim.x) {
        int row0 = tile * 128 + warp * 16 + nrow;
        int row1 = row0 + 8;
        const float* ar0 = A + (size_t)row0 * LDA + AOFF;
        const float* ar1 = A + (size_t)row1 * LDA + AOFF;

        float acc[NT][4];
#pragma unroll
        for (int nt = 0; nt < NT; nt++)
#pragma unroll
            for (int q = 0; q < 4; q++) acc[nt][q] = 0.0f;

#pragma unroll
        for (int kc = 0; kc < KC; kc++) {
            int kb = kc * 16 + k0;
            float x00, x01, x02, x03, x10, x11, x12, x13;
            if (VEC) {
                float2 p0 = (kb + 1 < K) ? *(const float2*)(ar0 + kb)
                                         : make_float2(kb < K ? ar0[kb] : 0.f, 0.f);
                float2 p1 = (kb + 1 < K) ? *(const float2*)(ar1 + kb)
                                         : make_float2(kb < K ? ar1[kb] : 0.f, 0.f);
                float2 p2 = (kb + 9 < K) ? *(const float2*)(ar0 + kb + 8)
                                         : make_float2(kb + 8 < K ? ar0[kb + 8] : 0.f, 0.f);
                float2 p3 = (kb + 9 < K) ? *(const float2*)(ar1 + kb + 8)
                                         : make_float2(kb + 8 < K ? ar1[kb + 8] : 0.f, 0.f);
                x00 = p0.x; x01 = p0.y; x10 = p1.x; x11 = p1.y;
                x02 = p2.x; x03 = p2.y; x12 = p3.x; x13 = p3.y;
            } else {
                x00 = (kb < K) ? ar0[kb] : 0.f;
                x01 = (kb + 1 < K) ? ar0[kb + 1] : 0.f;
                x10 = (kb < K) ? ar1[kb] : 0.f;
                x11 = (kb + 1 < K) ? ar1[kb + 1] : 0.f;
                x02 = (kb + 8 < K) ? ar0[kb + 8] : 0.f;
                x03 = (kb + 9 < K) ? ar0[kb + 9] : 0.f;
                x12 = (kb + 8 < K) ? ar1[kb + 8] : 0.f;
                x13 = (kb + 9 < K) ? ar1[kb + 9] : 0.f;
            }
            // hi fragments
            uint32_t ah0 = pack_bf16x2(x00, x01);
            uint32_t ah1 = pack_bf16x2(x10, x11);
            uint32_t ah2 = pack_bf16x2(x02, x03);
            uint32_t ah3 = pack_bf16x2(x12, x13);
            // lo fragments (residuals)
            float r00 = x00 - __bfloat162float(__float2bfloat16(x00));
            float r01 = x01 - __bfloat162float(__float2bfloat16(x01));
            float r10 = x10 - __bfloat162float(__float2bfloat16(x10));
            float r11 = x11 - __bfloat162float(__float2bfloat16(x11));
            float r02 = x02 - __bfloat162float(__float2bfloat16(x02));
            float r03 = x03 - __bfloat162float(__float2bfloat16(x03));
            float r12 = x12 - __bfloat162float(__float2bfloat16(x12));
            float r13 = x13 - __bfloat162float(__float2bfloat16(x13));
            uint32_t al0 = pack_bf16x2(r00, r01);
            uint32_t al1 = pack_bf16x2(r10, r11);
            uint32_t al2 = pack_bf16x2(r02, r03);
            uint32_t al3 = pack_bf16x2(r12, r13);

#pragma unroll
            for (int nt = 0; nt < NT; nt++) {
                int n = nt * 8 + nrow;
                const __nv_bfloat16* ph = sh + n * KS + kc * 16 + k0;
                const __nv_bfloat16* pl = sl + n * KS + kc * 16 + k0;
                uint32_t bh0 = *reinterpret_cast<const uint32_t*>(ph);
                uint32_t bh1 = *reinterpret_cast<const uint32_t*>(ph + 8);
                uint32_t bl0 = *reinterpret_cast<const uint32_t*>(pl);
                uint32_t bl1 = *reinterpret_cast<const uint32_t*>(pl + 8);
                mma_bf16(acc[nt], ah0, ah1, ah2, ah3, bh0, bh1);
                mma_bf16(acc[nt], ah0, ah1, ah2, ah3, bl0, bl1);
                mma_bf16(acc[nt], al0, al1, al2, al3, bh0, bh1);
            }
        }

        // ---- epilogue: bias + act + store ----
        float* c0 = C + (size_t)row0 * NOUT;
        float* c1 = C + (size_t)row1 * NOUT;
#pragma unroll
        for (int nt = 0; nt < NT; nt++) {
            int cc = nt * 8 + k0;  // output column (same (lane&3)*2 pattern as D frag)
            if (cc < NOUT) {
                float b0v = bias_s[cc], b1v = bias_s[cc + 1];
                float v0 = acc[nt][0] + b0v, v1 = acc[nt][1] + b1v;
                float v2 = acc[nt][2] + b0v, v3 = acc[nt][3] + b1v;
                if (ACT) {
                    v0 = v0 > 0.f ? v0 : 0.01f * v0;
                    v1 = v1 > 0.f ? v1 : 0.01f * v1;
                    v2 = v2 > 0.f ? v2 : 0.01f * v2;
                    v3 = v3 > 0.f ? v3 : 0.01f * v3;
                }
                *reinterpret_cast<float2*>(c0 + cc) = make_float2(v0, v1);
                *reinterpret_cast<float2*>(c1 + cc) = make_float2(v2, v3);
            }
        }
    }
}

// ---------------- denominator mu constant ----------------
__global__ void k_denmu(const float* __restrict__ mu) {
    int tid = threadIdx.x;
    __shared__ float S[10];
    if (tid < 10) {
        float s = 0.f;
        for (int t = 0; t < 65; t++) s += mu[t * 10 + tid];
        S[tid] = s * s;
    }
    __syncthreads();
    if (tid == 0) {
        float d = 0.f;
        for (int m = 0; m < 10; m++) d += S[m];
        g_denmu = d;
    }
}

// ---------------- bilinear grid sample ----------------
__global__ void k_gridsample(const float* __restrict__ img, const float* __restrict__ zern) {
    int p = blockIdx.x * blockDim.x + threadIdx.x;
    if (p >= NPIX) return;
    int y = p >> 8, x = p & 255;
    float px = zern[p * 35 + 0], py = zern[p * 35 + 1];
    float fx = 2.0f * ((float)x + px) / 255.0f - 1.0f;
    float fy = 2.0f * ((float)y + py) / 255.0f - 1.0f;
    float ix = ((fx + 1.0f) * 256.0f - 1.0f) * 0.5f;
    float iy = ((fy + 1.0f) * 256.0f - 1.0f) * 0.5f;
    ix = fminf(fmaxf(ix, 0.f), 255.f);
    iy = fminf(fmaxf(iy, 0.f), 255.f);
    float x0f = floorf(ix), y0f = floorf(iy);
    float wx = ix - x0f, wy = iy - y0f;
    int x0 = (int)x0f, y0 = (int)y0f;
    int x1 = min(x0 + 1, 255), y1 = min(y0 + 1, 255);
#pragma unroll
    for (int c = 0; c < 3; c++) {
        const float* im = img + c * NPIX;
        float g00 = im[y0 * 256 + x0], g01 = im[y0 * 256 + x1];
        float g10 = im[y1 * 256 + x0], g11 = im[y1 * 256 + x1];
        float top = g00 * (1.f - wx) + g01 * wx;
        float bot = g10 * (1.f - wx) + g11 * wx;
        g_tilt[c * NPIX + p] = top * (1.f - wy) + bot * wy;
    }
}

// ---------------- vertical pass ----------------
__global__ void k_vert(const float* __restrict__ basis_left) {
    extern __shared__ float smv[];
    float* coefS = smv;
    float* tiltS = smv + 100 * 257;
    float* Lsm = smv + 103 * 257;
    int w = blockIdx.x, tid = threadIdx.x;
    for (int i = tid; i < 650; i += 256) Lsm[i] = basis_left[i];
    for (int li = tid; li < 6400; li += 256) {
        int hh = li / 25, q = li % 25;
        float4 v = *(const float4*)&g_coef[(size_t)(hh * 256 + w) * 100 + q * 4];
        int c = q * 4;
        coefS[(c + 0) * 257 + hh] = v.x;
        coefS[(c + 1) * 257 + hh] = v.y;
        coefS[(c + 2) * 257 + hh] = v.z;
        coefS[(c + 3) * 257 + hh] = v.w;
    }
    for (int li = tid; li < 768; li += 256) {
        int k = li >> 8, hh = li & 255;
        tiltS[k * 257 + hh] = g_tilt[k * NPIX + hh * 256 + w];
    }
    __syncthreads();
    int h = tid;
    float acc[40];
#pragma unroll
    for (int q = 0; q < 40; q++) acc[q] = 0.f;
    for (int t = 0; t < 65; t++) {
        int r = h + t - 32;
        r = (r < 0) ? -r : ((r > 255) ? 510 - r : r);
        float s[10];
#pragma unroll
        for (int j = 0; j < 10; j++) s[j] = 0.f;
#pragma unroll
        for (int i = 0; i < 10; i++) {
            float Li = Lsm[t * 10 + i];
#pragma unroll
            for (int j = 0; j < 10; j++) s[j] += Li * coefS[(i * 10 + j) * 257 + r];
        }
        float t0 = tiltS[r], t1 = tiltS[257 + r], t2 = tiltS[514 + r];
#pragma unroll
        for (int j = 0; j < 10; j++) {
            acc[j] += t0 * s[j];
            acc[10 + j] += t1 * s[j];
            acc[20 + j] += t2 * s[j];
            acc[30 + j] += s[j];
        }
    }
#pragma unroll
    for (int p = 0; p < 40; p++) g_A[p * NPIX + h * 256 + w] = acc[p];
}

// ---------------- vertical mu pass ----------------
__global__ void k_vmu(const float* __restrict__ mu) {
    __shared__ float tiltS[3 * 257];
    __shared__ float Msm[650];
    int w = blockIdx.x, tid = threadIdx.x;
    for (int i = tid; i < 650; i += 256) Msm[i] = mu[i];
    for (int li = tid; li < 768; li += 256) {
        int k = li >> 8, hh = li & 255;
        tiltS[k * 257 + hh] = g_tilt[k * NPIX + hh * 256 + w];
    }
    __syncthreads();
    int h = tid;
    float acc[30];
#pragma unroll
    for (int q = 0; q < 30; q++) acc[q] = 0.f;
    for (int t = 0; t < 65; t++) {
        int r = h + t - 32;
        r = (r < 0) ? -r : ((r > 255) ? 510 - r : r);
        float t0 = tiltS[r], t1 = tiltS[257 + r], t2 = tiltS[514 + r];
#pragma unroll
        for (int m = 0; m < 10; m++) {
            float mv = Msm[t * 10 + m];
            acc[m] += mv * t0;
            acc[10 + m] += mv * t1;
            acc[20 + m] += mv * t2;
        }
    }
#pragma unroll
    for (int p = 0; p < 30; p++) g_Bmu[p * NPIX + h * 256 + w] = acc[p];
}

// ---------------- horizontal pass + divide ----------------
__global__ void k_horiz(const float* __restrict__ basis_right, const float* __restrict__ mu,
                        float* __restrict__ out) {
    extern __shared__ float smh[];
    float* P = smh;
    float* Rsm = smh + 70 * 193;
    float* Msm = Rsm + 650;
    int h = blockIdx.y;
    int w0 = blockIdx.x * 128;
    int tid = threadIdx.x;
    for (int i = tid; i < 650; i += 128) {
        Rsm[i] = basis_right[i];
        Msm[i] = mu[i];
    }
    int base = w0 - 32;
    if (base < 0) base = 0;
    int wend = w0 + 127 + 32;
    if (wend > 255) wend = 255;
    int width = wend - base + 1;
    for (int p = 0; p < 70; p++) {
        const float* src = (p < 40) ? (g_A + p * NPIX + h * 256) : (g_Bmu + (p - 40) * NPIX + h * 256);
        for (int c = tid; c < width; c += 128) P[p * 193 + c] = src[base + c];
    }
    __syncthreads();
    int w = w0 + tid;
    float n0a = 0.f, n1a = 0.f, n2a = 0.f, den = 0.f;
    for (int s = 0; s < 65; s++) {
        int wp = w + s - 32;
        wp = (wp < 0) ? -wp : ((wp > 255) ? 510 - wp : wp);
        int c = wp - base;
#pragma unroll
        for (int j = 0; j < 10; j++) {
            float Rv = Rsm[s * 10 + j];
            n0a += Rv * P[j * 193 + c];
            n1a += Rv * P[(10 + j) * 193 + c];
            n2a += Rv * P[(20 + j) * 193 + c];
            den += Rv * P[(30 + j) * 193 + c];
        }
#pragma unroll
        for (int m = 0; m < 10; m++) {
            float Mv = Msm[s * 10 + m];
            n0a += Mv * P[(40 + m) * 193 + c];
            n1a += Mv * P[(50 + m) * 193 + c];
            n2a += Mv * P[(60 + m) * 193 + c];
        }
    }
    den += g_denmu;
    out[0 * NPIX + h * 256 + w] = n0a / den;
    out[1 * NPIX + h * 256 + w] = n1a / den;
    out[2 * NPIX + h * 256 + w] = n2a / den;
}

// ---------------- launcher ----------------
extern "C" void kernel_launch(void* const* d_in, const int* in_sizes, int n_in,
                              void* d_out, int out_size) {
    const float* img  = (const float*)d_in[0];
    const float* zern = (const float*)d_in[1];
    const float* fc1w = (const float*)d_in[2];
    const float* fc1b = (const float*)d_in[3];
    const float* fc2w = (const float*)d_in[4];
    const float* fc2b = (const float*)d_in[5];
    const float* fc3w = (const float*)d_in[6];
    const float* fc3b = (const float*)d_in[7];
    const float* bl   = (const float*)d_in[8];
    const float* br   = (const float*)d_in[9];
    const float* mu   = (const float*)d_in[10];
    float* out = (float*)d_out;

    // smem: NP*KS*2 bf16 copies * 2B + NP*4B bias
    // l1: NP=200,KS=50  -> 200*50*2*2 + 800 = 40800
    // l2: NP=200,KS=210 -> 200*210*2*2 + 800 = 168800
    // l3: NP=104,KS=210 -> 104*210*2*2 + 416 = 87776
    auto l1 = k_mlp<200, 33, 35, 2, 1>;
    auto l2 = k_mlp<200, 200, 200, 0, 1>;
    auto l3 = k_mlp<100, 200, 200, 0, 0>;
    cudaFuncSetAttribute(l1, cudaFuncAttributeMaxDynamicSharedMemorySize, 40800);
    cudaFuncSetAttribute(l2, cudaFuncAttributeMaxDynamicSharedMemorySize, 168800);
    cudaFuncSetAttribute(l3, cudaFuncAttributeMaxDynamicSharedMemorySize, 87776);
    cudaFuncSetAttribute(k_vert, cudaFuncAttributeMaxDynamicSharedMemorySize, 108484);
    cudaFuncSetAttribute(k_horiz, cudaFuncAttributeMaxDynamicSharedMemorySize, 59240);

    float *h1, *h2, *coef;
    cudaGetSymbolAddress((void**)&h1, g_h1);
    cudaGetSymbolAddress((void**)&h2, g_h2);
    cudaGetSymbolAddress((void**)&coef, g_coef);

    k_denmu<<<1, 64>>>(mu);
    k_gridsample<<<256, 256>>>(img, zern);
    l1<<<148, 256, 40800>>>(zern, fc1w, fc1b, h1);
    l2<<<148, 256, 168800>>>(h1, fc2w, fc2b, h2);
    l3<<<148, 256, 87776>>>(h2, fc3w, fc3b, coef);
    k_vert<<<256, 256, 108484>>>(bl);
    k_vmu<<<256, 256>>>(mu);
    k_horiz<<<dim3(2, 256), 128, 59240>>>(br, mu, out);
}

// round 4
// speedup vs baseline: 1.7954x; 1.1470x over previous
#include <cuda_runtime.h>
#include <cuda_bf16.h>
#include <cstdint>

#define NPIX 65536

// ---------------- scratch (device globals; no allocation) ----------------
__device__ float g_tilt[3 * NPIX];
__device__ float g_h1[(size_t)NPIX * 200];
__device__ float g_h2[(size_t)NPIX * 200];
__device__ float g_coef[(size_t)NPIX * 100];
__device__ float g_A[40 * NPIX];
__device__ float g_Bmu[30 * NPIX];
__device__ float g_denmu;

// ---------------- warp-mma helpers ----------------
__device__ __forceinline__ void mma_bf16(float* c, uint32_t a0, uint32_t a1, uint32_t a2,
                                         uint32_t a3, uint32_t b0, uint32_t b1) {
    asm volatile(
        "mma.sync.aligned.m16n8k16.row.col.f32.bf16.bf16.f32 "
        "{%0,%1,%2,%3}, {%4,%5,%6,%7}, {%8,%9}, {%0,%1,%2,%3};"
        : "+f"(c[0]), "+f"(c[1]), "+f"(c[2]), "+f"(c[3])
        : "r"(a0), "r"(a1), "r"(a2), "r"(a3), "r"(b0), "r"(b1));
}
__device__ __forceinline__ uint32_t pack_bf16x2(float a, float b) {
    __nv_bfloat162 t;
    t.x = __float2bfloat16(a);
    t.y = __float2bfloat16(b);
    return *reinterpret_cast<uint32_t*>(&t);
}

// ================= split-bf16 warp-mma MLP layer =================
// 384 threads = 12 warps; each warp owns 16-row M-tiles, globally strided.
template <int NOUT, int K, int LDA, int AOFF, int ACT>
__global__ __launch_bounds__(384, 1) void k_mlp(const float* __restrict__ A,
                                                const float* __restrict__ W,
                                                const float* __restrict__ bias,
                                                float* __restrict__ C) {
    constexpr int NP = (NOUT + 7) & ~7;
    constexpr int NT = NP / 8;
    constexpr int KC = (K + 15) / 16;
    constexpr int KP = KC * 16;
    constexpr int KS = KP + 2;
    constexpr bool VEC = (LDA % 2 == 0) && (AOFF % 2 == 0);

    extern __shared__ char smraw[];
    __nv_bfloat16* sh = reinterpret_cast<__nv_bfloat16*>(smraw);
    __nv_bfloat16* sl = sh + NP * KS;
    float* bias_s = reinterpret_cast<float*>(sl + NP * KS);

    int tid = threadIdx.x;
    int lane = tid & 31, warp = tid >> 5;

    for (int idx = tid; idx < NP * KP; idx += 384) {
        int n = idx / KP, k = idx % KP;
        float v = (n < NOUT && k < K) ? W[n * K + k] : 0.0f;
        __nv_bfloat16 h = __float2bfloat16(v);
        float lo = v - __bfloat162float(h);
        sh[n * KS + k] = h;
        sl[n * KS + k] = __float2bfloat16(lo);
    }
    for (int i = tid; i < NP; i += 384) bias_s[i] = (i < NOUT) ? bias[i] : 0.0f;
    __syncthreads();

    const int k0 = (lane & 3) * 2;
    const int nrow = lane >> 2;
    const int gw = blockIdx.x * 12 + warp;
    const int gstride = gridDim.x * 12;

    for (int wt = gw; wt < 4096; wt += gstride) {
        int row0 = wt * 16 + nrow;
        int row1 = row0 + 8;
        const float* ar0 = A + (size_t)row0 * LDA + AOFF;
        const float* ar1 = A + (size_t)row1 * LDA + AOFF;

        float acc[NT][4];
#pragma unroll
        for (int nt = 0; nt < NT; nt++)
#pragma unroll
            for (int q = 0; q < 4; q++) acc[nt][q] = 0.0f;

#pragma unroll
        for (int kc = 0; kc < KC; kc++) {
            int kb = kc * 16 + k0;
            float x00, x01, x02, x03, x10, x11, x12, x13;
            if (VEC) {
                float2 p0 = (kb + 1 < K) ? *(const float2*)(ar0 + kb)
                                         : make_float2(kb < K ? ar0[kb] : 0.f, 0.f);
                float2 p1 = (kb + 1 < K) ? *(const float2*)(ar1 + kb)
                                         : make_float2(kb < K ? ar1[kb] : 0.f, 0.f);
                float2 p2 = (kb + 9 < K) ? *(const float2*)(ar0 + kb + 8)
                                         : make_float2(kb + 8 < K ? ar0[kb + 8] : 0.f, 0.f);
                float2 p3 = (kb + 9 < K) ? *(const float2*)(ar1 + kb + 8)
                                         : make_float2(kb + 8 < K ? ar1[kb + 8] : 0.f, 0.f);
                x00 = p0.x; x01 = p0.y; x10 = p1.x; x11 = p1.y;
                x02 = p2.x; x03 = p2.y; x12 = p3.x; x13 = p3.y;
            } else {
                x00 = (kb < K) ? ar0[kb] : 0.f;
                x01 = (kb + 1 < K) ? ar0[kb + 1] : 0.f;
                x10 = (kb < K) ? ar1[kb] : 0.f;
                x11 = (kb + 1 < K) ? ar1[kb + 1] : 0.f;
                x02 = (kb + 8 < K) ? ar0[kb + 8] : 0.f;
                x03 = (kb + 9 < K) ? ar0[kb + 9] : 0.f;
                x12 = (kb + 8 < K) ? ar1[kb + 8] : 0.f;
                x13 = (kb + 9 < K) ? ar1[kb + 9] : 0.f;
            }
            uint32_t ah0 = pack_bf16x2(x00, x01);
            uint32_t ah1 = pack_bf16x2(x10, x11);
            uint32_t ah2 = pack_bf16x2(x02, x03);
            uint32_t ah3 = pack_bf16x2(x12, x13);
            float r00 = x00 - __bfloat162float(__float2bfloat16(x00));
            float r01 = x01 - __bfloat162float(__float2bfloat16(x01));
            float r10 = x10 - __bfloat162float(__float2bfloat16(x10));
            float r11 = x11 - __bfloat162float(__float2bfloat16(x11));
            float r02 = x02 - __bfloat162float(__float2bfloat16(x02));
            float r03 = x03 - __bfloat162float(__float2bfloat16(x03));
            float r12 = x12 - __bfloat162float(__float2bfloat16(x12));
            float r13 = x13 - __bfloat162float(__float2bfloat16(x13));
            uint32_t al0 = pack_bf16x2(r00, r01);
            uint32_t al1 = pack_bf16x2(r10, r11);
            uint32_t al2 = pack_bf16x2(r02, r03);
            uint32_t al3 = pack_bf16x2(r12, r13);

#pragma unroll
            for (int nt = 0; nt < NT; nt++) {
                int n = nt * 8 + nrow;
                const __nv_bfloat16* ph = sh + n * KS + kc * 16 + k0;
                const __nv_bfloat16* pl = sl + n * KS + kc * 16 + k0;
                uint32_t bh0 = *reinterpret_cast<const uint32_t*>(ph);
                uint32_t bh1 = *reinterpret_cast<const uint32_t*>(ph + 8);
                uint32_t bl0 = *reinterpret_cast<const uint32_t*>(pl);
                uint32_t bl1 = *reinterpret_cast<const uint32_t*>(pl + 8);
                mma_bf16(acc[nt], ah0, ah1, ah2, ah3, bh0, bh1);
                mma_bf16(acc[nt], ah0, ah1, ah2, ah3, bl0, bl1);
                mma_bf16(acc[nt], al0, al1, al2, al3, bh0, bh1);
            }
        }

        float* c0 = C + (size_t)row0 * NOUT;
        float* c1 = C + (size_t)row1 * NOUT;
#pragma unroll
        for (int nt = 0; nt < NT; nt++) {
            int cc = nt * 8 + k0;
            if (cc < NOUT) {
                float b0v = bias_s[cc], b1v = bias_s[cc + 1];
                float v0 = acc[nt][0] + b0v, v1 = acc[nt][1] + b1v;
                float v2 = acc[nt][2] + b0v, v3 = acc[nt][3] + b1v;
                if (ACT) {
                    v0 = v0 > 0.f ? v0 : 0.01f * v0;
                    v1 = v1 > 0.f ? v1 : 0.01f * v1;
                    v2 = v2 > 0.f ? v2 : 0.01f * v2;
                    v3 = v3 > 0.f ? v3 : 0.01f * v3;
                }
                *reinterpret_cast<float2*>(c0 + cc) = make_float2(v0, v1);
                *reinterpret_cast<float2*>(c1 + cc) = make_float2(v2, v3);
            }
        }
    }
}

// ---------------- denominator mu constant ----------------
__global__ void k_denmu(const float* __restrict__ mu) {
    int tid = threadIdx.x;
    __shared__ float S[10];
    if (tid < 10) {
        float s = 0.f;
        for (int t = 0; t < 65; t++) s += mu[t * 10 + tid];
        S[tid] = s * s;
    }
    __syncthreads();
    if (tid == 0) {
        float d = 0.f;
        for (int m = 0; m < 10; m++) d += S[m];
        g_denmu = d;
    }
}

// ---------------- bilinear grid sample ----------------
__global__ void k_gridsample(const float* __restrict__ img, const float* __restrict__ zern) {
    int p = blockIdx.x * blockDim.x + threadIdx.x;
    if (p >= NPIX) return;
    int y = p >> 8, x = p & 255;
    float px = zern[p * 35 + 0], py = zern[p * 35 + 1];
    float fx = 2.0f * ((float)x + px) / 255.0f - 1.0f;
    float fy = 2.0f * ((float)y + py) / 255.0f - 1.0f;
    float ix = ((fx + 1.0f) * 256.0f - 1.0f) * 0.5f;
    float iy = ((fy + 1.0f) * 256.0f - 1.0f) * 0.5f;
    ix = fminf(fmaxf(ix, 0.f), 255.f);
    iy = fminf(fmaxf(iy, 0.f), 255.f);
    float x0f = floorf(ix), y0f = floorf(iy);
    float wx = ix - x0f, wy = iy - y0f;
    int x0 = (int)x0f, y0 = (int)y0f;
    int x1 = min(x0 + 1, 255), y1 = min(y0 + 1, 255);
#pragma unroll
    for (int c = 0; c < 3; c++) {
        const float* im = img + c * NPIX;
        float g00 = im[y0 * 256 + x0], g01 = im[y0 * 256 + x1];
        float g10 = im[y1 * 256 + x0], g11 = im[y1 * 256 + x1];
        float top = g00 * (1.f - wx) + g01 * wx;
        float bot = g10 * (1.f - wx) + g11 * wx;
        g_tilt[c * NPIX + p] = top * (1.f - wy) + bot * wy;
    }
}

// ---------------- vertical pass: 2 outputs (h, h+1) per thread ----------------
// coef staged parity-split: coefE (even rows), coefO (odd rows), stride 102.
// Lane stride = 1 row -> conflict-free float2 LDS; reflection preserves parity
// so the E/O selection is warp-uniform per iteration.
__global__ __launch_bounds__(128) void k_vert(const float* __restrict__ basis_left) {
    extern __shared__ float smv[];
    float* coefE = smv;                      // 128*102
    float* coefO = smv + 128 * 102;          // 128*102
    float* tiltS = coefO + 128 * 102;        // 3*257
    float* Lsm = tiltS + 3 * 257;            // 650
    int w = blockIdx.x, tid = threadIdx.x;
    for (int i = tid; i < 650; i += 128) Lsm[i] = basis_left[i];
    for (int li = tid; li < 6400; li += 128) {
        int hh = li / 25, q = li % 25;
        float4 v = *(const float4*)&g_coef[(size_t)(hh * 256 + w) * 100 + q * 4];
        float* dst = ((hh & 1) ? coefO : coefE) + (hh >> 1) * 102 + q * 4;
        dst[0] = v.x; dst[1] = v.y; dst[2] = v.z; dst[3] = v.w;
    }
    for (int li = tid; li < 768; li += 128) {
        int k = li >> 8, hh = li & 255;
        tiltS[k * 257 + hh] = g_tilt[k * NPIX + hh * 256 + w];
    }
    __syncthreads();

    const int h1 = 2 * tid;
    float acc1[40], acc2[40];
#pragma unroll
    for (int p = 0; p < 40; p++) { acc1[p] = 0.f; acc2[p] = 0.f; }

#pragma unroll 2
    for (int ro = -32; ro <= 33; ro++) {
        int r = h1 + ro;
        r = (r < 0) ? -r : ((r > 255) ? 510 - r : r);
        int t1 = ro + 32, t2 = ro + 31;                    // taps for h1, h1+1
        bool va = (t1 <= 64), vb = (t2 >= 0);
        int t1c = va ? t1 : 64, t2c = vb ? t2 : 0;
        const float* crow = ((r & 1) ? coefO : coefE) + (r >> 1) * 102;
        float s1[10], s2[10];
#pragma unroll
        for (int j = 0; j < 10; j++) { s1[j] = 0.f; s2[j] = 0.f; }
#pragma unroll
        for (int i = 0; i < 10; i++) {
            float L1 = va ? Lsm[t1c * 10 + i] : 0.f;
            float L2 = vb ? Lsm[t2c * 10 + i] : 0.f;
#pragma unroll
            for (int u = 0; u < 5; u++) {
                float2 cc = *(const float2*)&crow[i * 10 + 2 * u];
                s1[2 * u]     += L1 * cc.x;
                s1[2 * u + 1] += L1 * cc.y;
                s2[2 * u]     += L2 * cc.x;
                s2[2 * u + 1] += L2 * cc.y;
            }
        }
        float T0 = tiltS[r], T1 = tiltS[257 + r], T2 = tiltS[514 + r];
#pragma unroll
        for (int j = 0; j < 10; j++) {
            acc1[j]      += T0 * s1[j];
            acc1[10 + j] += T1 * s1[j];
            acc1[20 + j] += T2 * s1[j];
            acc1[30 + j] += s1[j];
            acc2[j]      += T0 * s2[j];
            acc2[10 + j] += T1 * s2[j];
            acc2[20 + j] += T2 * s2[j];
            acc2[30 + j] += s2[j];
        }
    }
#pragma unroll
    for (int p = 0; p < 40; p++) {
        g_A[p * NPIX + h1 * 256 + w] = acc1[p];
        g_A[p * NPIX + (h1 + 1) * 256 + w] = acc2[p];
    }
}

// ---------------- vertical mu pass ----------------
__global__ void k_vmu(const float* __restrict__ mu) {
    __shared__ float tiltS[3 * 257];
    __shared__ float Msm[650];
    int w = blockIdx.x, tid = threadIdx.x;
    for (int i = tid; i < 650; i += 256) Msm[i] = mu[i];
    for (int li = tid; li < 768; li += 256) {
        int k = li >> 8, hh = li & 255;
        tiltS[k * 257 + hh] = g_tilt[k * NPIX + hh * 256 + w];
    }
    __syncthreads();
    int h = tid;
    float acc[30];
#pragma unroll
    for (int q = 0; q < 30; q++) acc[q] = 0.f;
    for (int t = 0; t < 65; t++) {
        int r = h + t - 32;
        r = (r < 0) ? -r : ((r > 255) ? 510 - r : r);
        float t0 = tiltS[r], t1 = tiltS[257 + r], t2 = tiltS[514 + r];
#pragma unroll
        for (int m = 0; m < 10; m++) {
            float mv = Msm[t * 10 + m];
            acc[m] += mv * t0;
            acc[10 + m] += mv * t1;
            acc[20 + m] += mv * t2;
        }
    }
#pragma unroll
    for (int p = 0; p < 30; p++) g_Bmu[p * NPIX + h * 256 + w] = acc[p];
}

// ---------------- horizontal pass: 2 outputs (w, w+1) per thread ----------------
__global__ __launch_bounds__(128) void k_horiz(const float* __restrict__ basis_right,
                                               const float* __restrict__ mu,
                                               float* __restrict__ out) {
    extern __shared__ float smh[];
    float* P = smh;                 // 70 * 258 (full row, all planes)
    float* Rsm = P + 70 * 258;      // 650
    float* Msm = Rsm + 650;         // 650
    int h = blockIdx.x, tid = threadIdx.x;
    for (int i = tid; i < 650; i += 128) {
        Rsm[i] = basis_right[i];
        Msm[i] = mu[i];
    }
    for (int p = 0; p < 40; p++)
        for (int c = tid; c < 256; c += 128) P[p * 258 + c] = g_A[p * NPIX + h * 256 + c];
    for (int p = 0; p < 30; p++)
        for (int c = tid; c < 256; c += 128) P[(40 + p) * 258 + c] = g_Bmu[p * NPIX + h * 256 + c];
    __syncthreads();

    const int w0 = 2 * tid;
    float n0a = 0, n0b = 0, n1a = 0, n1b = 0, n2a = 0, n2b = 0, dna = 0, dnb = 0;

    for (int ke = 0; ke <= 64; ke += 2) {
        int c = w0 + ke - 32;
        bool fast = (c >= 0) && (c <= 254);
        int ca = (c < 0) ? -c : ((c > 255) ? 510 - c : c);
        int cd = c + 1;
        int cb = (cd < 0) ? -cd : ((cd > 255) ? 510 - cd : cd);

        float Rm[10], R0[10], Rp[10], Mm[10], M0[10], Mp[10];
#pragma unroll
        for (int j = 0; j < 10; j++) {
            R0[j] = Rsm[ke * 10 + j];
            M0[j] = Msm[ke * 10 + j];
            Rp[j] = (ke < 64) ? Rsm[(ke + 1) * 10 + j] : 0.f;
            Mp[j] = (ke < 64) ? Msm[(ke + 1) * 10 + j] : 0.f;
            Rm[j] = (ke > 0) ? Rsm[(ke - 1) * 10 + j] : 0.f;
            Mm[j] = (ke > 0) ? Msm[(ke - 1) * 10 + j] : 0.f;
        }
#pragma unroll
        for (int j = 0; j < 10; j++) {
            float2 g;
#define LOADP(p) (fast ? *(const float2*)&P[(p) * 258 + c] \
                       : make_float2(P[(p) * 258 + ca], P[(p) * 258 + cb]))
            g = LOADP(j);
            n0a += R0[j] * g.x + Rp[j] * g.y;  n0b += Rm[j] * g.x + R0[j] * g.y;
            g = LOADP(10 + j);
            n1a += R0[j] * g.x + Rp[j] * g.y;  n1b += Rm[j] * g.x + R0[j] * g.y;
            g = LOADP(20 + j);
            n2a += R0[j] * g.x + Rp[j] * g.y;  n2b += Rm[j] * g.x + R0[j] * g.y;
            g = LOADP(30 + j);
            dna += R0[j] * g.x + Rp[j] * g.y;  dnb += Rm[j] * g.x + R0[j] * g.y;
            g = LOADP(40 + j);
            n0a += M0[j] * g.x + Mp[j] * g.y;  n0b += Mm[j] * g.x + M0[j] * g.y;
            g = LOADP(50 + j);
            n1a += M0[j] * g.x + Mp[j] * g.y;  n1b += Mm[j] * g.x + M0[j] * g.y;
            g = LOADP(60 + j);
            n2a += M0[j] * g.x + Mp[j] * g.y;  n2b += Mm[j] * g.x + M0[j] * g.y;
#undef LOADP
        }
    }
    float dmu = g_denmu;
    dna += dmu;
    dnb += dmu;
    size_t base = (size_t)h * 256 + w0;
    *reinterpret_cast<float2*>(&out[0 * NPIX + base]) = make_float2(n0a / dna, n0b / dnb);
    *reinterpret_cast<float2*>(&out[1 * NPIX + base]) = make_float2(n1a / dna, n1b / dnb);
    *reinterpret_cast<float2*>(&out[2 * NPIX + base]) = make_float2(n2a / dna, n2b / dnb);
}

// ---------------- launcher ----------------
extern "C" void kernel_launch(void* const* d_in, const int* in_sizes, int n_in,
                              void* d_out, int out_size) {
    const float* img  = (const float*)d_in[0];
    const float* zern = (const float*)d_in[1];
    const float* fc1w = (const float*)d_in[2];
    const float* fc1b = (const float*)d_in[3];
    const float* fc2w = (const float*)d_in[4];
    const float* fc2b = (const float*)d_in[5];
    const float* fc3w = (const float*)d_in[6];
    const float* fc3b = (const float*)d_in[7];
    const float* bl   = (const float*)d_in[8];
    const float* br   = (const float*)d_in[9];
    const float* mu   = (const float*)d_in[10];
    float* out = (float*)d_out;

    auto l1 = k_mlp<200, 33, 35, 2, 1>;
    auto l2 = k_mlp<200, 200, 200, 0, 1>;
    auto l3 = k_mlp<100, 200, 200, 0, 0>;
    cudaFuncSetAttribute(l1, cudaFuncAttributeMaxDynamicSharedMemorySize, 40800);
    cudaFuncSetAttribute(l2, cudaFuncAttributeMaxDynamicSharedMemorySize, 168800);
    cudaFuncSetAttribute(l3, cudaFuncAttributeMaxDynamicSharedMemorySize, 87776);
    // vert: 2*128*102*4 + 3*257*4 + 650*4 = 110132
    cudaFuncSetAttribute(k_vert, cudaFuncAttributeMaxDynamicSharedMemorySize, 110132);
    // horiz: 70*258*4 + 2*650*4 = 77440
    cudaFuncSetAttribute(k_horiz, cudaFuncAttributeMaxDynamicSharedMemorySize, 77440);

    float *h1, *h2, *coef;
    cudaGetSymbolAddress((void**)&h1, g_h1);
    cudaGetSymbolAddress((void**)&h2, g_h2);
    cudaGetSymbolAddress((void**)&coef, g_coef);

    k_denmu<<<1, 64>>>(mu);
    k_gridsample<<<256, 256>>>(img, zern);
    l1<<<148, 384, 40800>>>(zern, fc1w, fc1b, h1);
    l2<<<148, 384, 168800>>>(h1, fc2w, fc2b, h2);
    l3<<<148, 384, 87776>>>(h2, fc3w, fc3b, coef);
    k_vert<<<256, 128, 110132>>>(bl);
    k_vmu<<<256, 256>>>(mu);
    k_horiz<<<256, 128, 77440>>>(br, mu, out);
}

// round 5
// speedup vs baseline: 1.9507x; 1.0865x over previous
#include <cuda_runtime.h>
#include <cuda_bf16.h>
#include <cstdint>

#define NPIX 65536

// ---------------- scratch (device globals; no allocation) ----------------
__device__ float g_tilt[3 * NPIX];
__device__ float g_h1[(size_t)NPIX * 200];
__device__ float g_h2[(size_t)NPIX * 200];
__device__ float g_coef[(size_t)NPIX * 100];
__device__ float g_A[40 * NPIX];
__device__ float g_Bmu[30 * NPIX];
__device__ float g_denmu;

// ---------------- warp-mma helpers ----------------
__device__ __forceinline__ void mma_bf16(float* c, uint32_t a0, uint32_t a1, uint32_t a2,
                                         uint32_t a3, uint32_t b0, uint32_t b1) {
    asm volatile(
        "mma.sync.aligned.m16n8k16.row.col.f32.bf16.bf16.f32 "
        "{%0,%1,%2,%3}, {%4,%5,%6,%7}, {%8,%9}, {%0,%1,%2,%3};"
        : "+f"(c[0]), "+f"(c[1]), "+f"(c[2]), "+f"(c[3])
        : "r"(a0), "r"(a1), "r"(a2), "r"(a3), "r"(b0), "r"(b1));
}
__device__ __forceinline__ uint32_t pack_bf16x2(float a, float b) {
    __nv_bfloat162 t;
    t.x = __float2bfloat16(a);
    t.y = __float2bfloat16(b);
    return *reinterpret_cast<uint32_t*>(&t);
}

// ---------------- per-warp MLP body over an N-subrange ----------------
template <int NOUT, int K, int LDA, int AOFF, int ACT, int NTH>
__device__ __forceinline__ void mlp_body(const float* __restrict__ A, float* __restrict__ C,
                                         const __nv_bfloat16* sh, const __nv_bfloat16* sl,
                                         const float* bias_s, int lane, int gp, int gstride,
                                         int noff) {
    constexpr int KC = (K + 15) / 16;
    constexpr int KP = KC * 16;
    constexpr int KS = KP + 8;   // row stride (elems): KS/2 words == 4 (mod 8) -> conflict-free
    constexpr bool VEC = (LDA % 2 == 0) && (AOFF % 2 == 0);
    const int k0 = (lane & 3) * 2;
    const int nrow = lane >> 2;

    for (int wt = gp; wt < 4096; wt += gstride) {
        int row0 = wt * 16 + nrow;
        int row1 = row0 + 8;
        const float* ar0 = A + (size_t)row0 * LDA + AOFF;
        const float* ar1 = A + (size_t)row1 * LDA + AOFF;

        float acc[NTH][4];
#pragma unroll
        for (int nt = 0; nt < NTH; nt++)
#pragma unroll
            for (int q = 0; q < 4; q++) acc[nt][q] = 0.0f;

#pragma unroll
        for (int kc = 0; kc < KC; kc++) {
            int kb = kc * 16 + k0;
            float x00, x01, x02, x03, x10, x11, x12, x13;
            if (VEC) {
                float2 p0 = (kb + 1 < K) ? *(const float2*)(ar0 + kb)
                                         : make_float2(kb < K ? ar0[kb] : 0.f, 0.f);
                float2 p1 = (kb + 1 < K) ? *(const float2*)(ar1 + kb)
                                         : make_float2(kb < K ? ar1[kb] : 0.f, 0.f);
                float2 p2 = (kb + 9 < K) ? *(const float2*)(ar0 + kb + 8)
                                         : make_float2(kb + 8 < K ? ar0[kb + 8] : 0.f, 0.f);
                float2 p3 = (kb + 9 < K) ? *(const float2*)(ar1 + kb + 8)
                                         : make_float2(kb + 8 < K ? ar1[kb + 8] : 0.f, 0.f);
                x00 = p0.x; x01 = p0.y; x10 = p1.x; x11 = p1.y;
                x02 = p2.x; x03 = p2.y; x12 = p3.x; x13 = p3.y;
            } else {
                x00 = (kb < K) ? ar0[kb] : 0.f;
                x01 = (kb + 1 < K) ? ar0[kb + 1] : 0.f;
                x10 = (kb < K) ? ar1[kb] : 0.f;
                x11 = (kb + 1 < K) ? ar1[kb + 1] : 0.f;
                x02 = (kb + 8 < K) ? ar0[kb + 8] : 0.f;
                x03 = (kb + 9 < K) ? ar0[kb + 9] : 0.f;
                x12 = (kb + 8 < K) ? ar1[kb + 8] : 0.f;
                x13 = (kb + 9 < K) ? ar1[kb + 9] : 0.f;
            }
            uint32_t ah0 = pack_bf16x2(x00, x01);
            uint32_t ah1 = pack_bf16x2(x10, x11);
            uint32_t ah2 = pack_bf16x2(x02, x03);
            uint32_t ah3 = pack_bf16x2(x12, x13);
            float r00 = x00 - __bfloat162float(__float2bfloat16(x00));
            float r01 = x01 - __bfloat162float(__float2bfloat16(x01));
            float r10 = x10 - __bfloat162float(__float2bfloat16(x10));
            float r11 = x11 - __bfloat162float(__float2bfloat16(x11));
            float r02 = x02 - __bfloat162float(__float2bfloat16(x02));
            float r03 = x03 - __bfloat162float(__float2bfloat16(x03));
            float r12 = x12 - __bfloat162float(__float2bfloat16(x12));
            float r13 = x13 - __bfloat162float(__float2bfloat16(x13));
            uint32_t al0 = pack_bf16x2(r00, r01);
            uint32_t al1 = pack_bf16x2(r10, r11);
            uint32_t al2 = pack_bf16x2(r02, r03);
            uint32_t al3 = pack_bf16x2(r12, r13);

#pragma unroll
            for (int nt = 0; nt < NTH; nt++) {
                int n = noff + nt * 8 + nrow;
                const __nv_bfloat16* ph = sh + n * KS + kc * 16 + k0;
                const __nv_bfloat16* pl = sl + n * KS + kc * 16 + k0;
                uint32_t bh0 = *reinterpret_cast<const uint32_t*>(ph);
                uint32_t bh1 = *reinterpret_cast<const uint32_t*>(ph + 8);
                uint32_t bl0 = *reinterpret_cast<const uint32_t*>(pl);
                uint32_t bl1 = *reinterpret_cast<const uint32_t*>(pl + 8);
                mma_bf16(acc[nt], ah0, ah1, ah2, ah3, bh0, bh1);
                mma_bf16(acc[nt], ah0, ah1, ah2, ah3, bl0, bl1);
                mma_bf16(acc[nt], al0, al1, al2, al3, bh0, bh1);
            }
        }

        float* c0 = C + (size_t)row0 * NOUT;
        float* c1 = C + (size_t)row1 * NOUT;
#pragma unroll
        for (int nt = 0; nt < NTH; nt++) {
            int cc = noff + nt * 8 + k0;
            if (cc < NOUT) {
                float b0v = bias_s[cc], b1v = bias_s[cc + 1];
                float v0 = acc[nt][0] + b0v, v1 = acc[nt][1] + b1v;
                float v2 = acc[nt][2] + b0v, v3 = acc[nt][3] + b1v;
                if (ACT) {
                    v0 = v0 > 0.f ? v0 : 0.01f * v0;
                    v1 = v1 > 0.f ? v1 : 0.01f * v1;
                    v2 = v2 > 0.f ? v2 : 0.01f * v2;
                    v3 = v3 > 0.f ? v3 : 0.01f * v3;
                }
                *reinterpret_cast<float2*>(c0 + cc) = make_float2(v0, v1);
                *reinterpret_cast<float2*>(c1 + cc) = make_float2(v2, v3);
            }
        }
    }
}

// ================= split-bf16 warp-mma MLP layer =================
// 512 threads = 16 warps = 8 warp pairs; pair shares a 16-row M-tile, halves split N.
template <int NOUT, int K, int LDA, int AOFF, int ACT>
__global__ __launch_bounds__(512, 1) void k_mlp(const float* __restrict__ A,
                                                const float* __restrict__ W,
                                                const float* __restrict__ bias,
                                                float* __restrict__ C) {
    constexpr int NP = (NOUT + 7) & ~7;
    constexpr int NT = NP / 8;
    constexpr int NT0 = (NT + 1) / 2;
    constexpr int NT1 = NT - NT0;
    constexpr int KC = (K + 15) / 16;
    constexpr int KP = KC * 16;
    constexpr int KS = KP + 8;

    extern __shared__ char smraw[];
    __nv_bfloat16* sh = reinterpret_cast<__nv_bfloat16*>(smraw);
    __nv_bfloat16* sl = sh + NP * KS;
    float* bias_s = reinterpret_cast<float*>(sl + NP * KS);

    int tid = threadIdx.x;
    int lane = tid & 31, warp = tid >> 5;

    for (int idx = tid; idx < NP * KP; idx += 512) {
        int n = idx / KP, k = idx % KP;
        float v = (n < NOUT && k < K) ? W[n * K + k] : 0.0f;
        __nv_bfloat16 h = __float2bfloat16(v);
        float lo = v - __bfloat162float(h);
        sh[n * KS + k] = h;
        sl[n * KS + k] = __float2bfloat16(lo);
    }
    for (int i = tid; i < NP; i += 512) bias_s[i] = (i < NOUT) ? bias[i] : 0.0f;
    __syncthreads();

    const int gp = blockIdx.x * 8 + (warp >> 1);
    const int gstride = gridDim.x * 8;
    if ((warp & 1) == 0)
        mlp_body<NOUT, K, LDA, AOFF, ACT, NT0>(A, C, sh, sl, bias_s, lane, gp, gstride, 0);
    else
        mlp_body<NOUT, K, LDA, AOFF, ACT, NT1>(A, C, sh, sl, bias_s, lane, gp, gstride, NT0 * 8);
}

// ---------------- denominator mu constant ----------------
__global__ void k_denmu(const float* __restrict__ mu) {
    int tid = threadIdx.x;
    __shared__ float S[10];
    if (tid < 10) {
        float s = 0.f;
        for (int t = 0; t < 65; t++) s += mu[t * 10 + tid];
        S[tid] = s * s;
    }
    __syncthreads();
    if (tid == 0) {
        float d = 0.f;
        for (int m = 0; m < 10; m++) d += S[m];
        g_denmu = d;
    }
}

// ---------------- bilinear grid sample ----------------
__global__ void k_gridsample(const float* __restrict__ img, const float* __restrict__ zern) {
    int p = blockIdx.x * blockDim.x + threadIdx.x;
    if (p >= NPIX) return;
    int y = p >> 8, x = p & 255;
    float px = zern[p * 35 + 0], py = zern[p * 35 + 1];
    float fx = 2.0f * ((float)x + px) / 255.0f - 1.0f;
    float fy = 2.0f * ((float)y + py) / 255.0f - 1.0f;
    float ix = ((fx + 1.0f) * 256.0f - 1.0f) * 0.5f;
    float iy = ((fy + 1.0f) * 256.0f - 1.0f) * 0.5f;
    ix = fminf(fmaxf(ix, 0.f), 255.f);
    iy = fminf(fmaxf(iy, 0.f), 255.f);
    float x0f = floorf(ix), y0f = floorf(iy);
    float wx = ix - x0f, wy = iy - y0f;
    int x0 = (int)x0f, y0 = (int)y0f;
    int x1 = min(x0 + 1, 255), y1 = min(y0 + 1, 255);
#pragma unroll
    for (int c = 0; c < 3; c++) {
        const float* im = img + c * NPIX;
        float g00 = im[y0 * 256 + x0], g01 = im[y0 * 256 + x1];
        float g10 = im[y1 * 256 + x0], g11 = im[y1 * 256 + x1];
        float top = g00 * (1.f - wx) + g01 * wx;
        float bot = g10 * (1.f - wx) + g11 * wx;
        g_tilt[c * NPIX + p] = top * (1.f - wy) + bot * wy;
    }
}

// ---------------- vertical pass: 2 outputs (h, h+1) per thread ----------------
__global__ __launch_bounds__(128) void k_vert(const float* __restrict__ basis_left) {
    extern __shared__ float smv[];
    float* coefE = smv;
    float* coefO = smv + 128 * 102;
    float* tiltS = coefO + 128 * 102;
    float* Lsm = tiltS + 3 * 257;
    int w = blockIdx.x, tid = threadIdx.x;
    for (int i = tid; i < 650; i += 128) Lsm[i] = basis_left[i];
    for (int li = tid; li < 6400; li += 128) {
        int hh = li / 25, q = li % 25;
        float4 v = *(const float4*)&g_coef[(size_t)(hh * 256 + w) * 100 + q * 4];
        float* dst = ((hh & 1) ? coefO : coefE) + (hh >> 1) * 102 + q * 4;
        dst[0] = v.x; dst[1] = v.y; dst[2] = v.z; dst[3] = v.w;
    }
    for (int li = tid; li < 768; li += 128) {
        int k = li >> 8, hh = li & 255;
        tiltS[k * 257 + hh] = g_tilt[k * NPIX + hh * 256 + w];
    }
    __syncthreads();

    const int h1 = 2 * tid;
    float acc1[40], acc2[40];
#pragma unroll
    for (int p = 0; p < 40; p++) { acc1[p] = 0.f; acc2[p] = 0.f; }

#pragma unroll 2
    for (int ro = -32; ro <= 33; ro++) {
        int r = h1 + ro;
        r = (r < 0) ? -r : ((r > 255) ? 510 - r : r);
        int t1 = ro + 32, t2 = ro + 31;
        bool va = (t1 <= 64), vb = (t2 >= 0);
        int t1c = va ? t1 : 64, t2c = vb ? t2 : 0;
        const float* crow = ((r & 1) ? coefO : coefE) + (r >> 1) * 102;
        float s1[10], s2[10];
#pragma unroll
        for (int j = 0; j < 10; j++) { s1[j] = 0.f; s2[j] = 0.f; }
#pragma unroll
        for (int i = 0; i < 10; i++) {
            float L1 = va ? Lsm[t1c * 10 + i] : 0.f;
            float L2 = vb ? Lsm[t2c * 10 + i] : 0.f;
#pragma unroll
            for (int u = 0; u < 5; u++) {
                float2 cc = *(const float2*)&crow[i * 10 + 2 * u];
                s1[2 * u]     += L1 * cc.x;
                s1[2 * u + 1] += L1 * cc.y;
                s2[2 * u]     += L2 * cc.x;
                s2[2 * u + 1] += L2 * cc.y;
            }
        }
        float T0 = tiltS[r], T1 = tiltS[257 + r], T2 = tiltS[514 + r];
#pragma unroll
        for (int j = 0; j < 10; j++) {
            acc1[j]      += T0 * s1[j];
            acc1[10 + j] += T1 * s1[j];
            acc1[20 + j] += T2 * s1[j];
            acc1[30 + j] += s1[j];
            acc2[j]      += T0 * s2[j];
            acc2[10 + j] += T1 * s2[j];
            acc2[20 + j] += T2 * s2[j];
            acc2[30 + j] += s2[j];
        }
    }
#pragma unroll
    for (int p = 0; p < 40; p++) {
        g_A[p * NPIX + h1 * 256 + w] = acc1[p];
        g_A[p * NPIX + (h1 + 1) * 256 + w] = acc2[p];
    }
}

// ---------------- vertical mu pass ----------------
__global__ void k_vmu(const float* __restrict__ mu) {
    __shared__ float tiltS[3 * 257];
    __shared__ float Msm[650];
    int w = blockIdx.x, tid = threadIdx.x;
    for (int i = tid; i < 650; i += 256) Msm[i] = mu[i];
    for (int li = tid; li < 768; li += 256) {
        int k = li >> 8, hh = li & 255;
        tiltS[k * 257 + hh] = g_tilt[k * NPIX + hh * 256 + w];
    }
    __syncthreads();
    int h = tid;
    float acc[30];
#pragma unroll
    for (int q = 0; q < 30; q++) acc[q] = 0.f;
    for (int t = 0; t < 65; t++) {
        int r = h + t - 32;
        r = (r < 0) ? -r : ((r > 255) ? 510 - r : r);
        float t0 = tiltS[r], t1 = tiltS[257 + r], t2 = tiltS[514 + r];
#pragma unroll
        for (int m = 0; m < 10; m++) {
            float mv = Msm[t * 10 + m];
            acc[m] += mv * t0;
            acc[10 + m] += mv * t1;
            acc[20 + m] += mv * t2;
        }
    }
#pragma unroll
    for (int p = 0; p < 30; p++) g_Bmu[p * NPIX + h * 256 + w] = acc[p];
}

// ---------------- horizontal pass: 2 outputs (w, w+1) per thread ----------------
__global__ __launch_bounds__(128) void k_horiz(const float* __restrict__ basis_right,
                                               const float* __restrict__ mu,
                                               float* __restrict__ out) {
    extern __shared__ float smh[];
    float* P = smh;
    float* Rsm = P + 70 * 258;
    float* Msm = Rsm + 650;
    int h = blockIdx.x, tid = threadIdx.x;
    for (int i = tid; i < 650; i += 128) {
        Rsm[i] = basis_right[i];
        Msm[i] = mu[i];
    }
    for (int p = 0; p < 40; p++)
        for (int c = tid; c < 256; c += 128) P[p * 258 + c] = g_A[p * NPIX + h * 256 + c];
    for (int p = 0; p < 30; p++)
        for (int c = tid; c < 256; c += 128) P[(40 + p) * 258 + c] = g_Bmu[p * NPIX + h * 256 + c];
    __syncthreads();

    const int w0 = 2 * tid;
    float n0a = 0, n0b = 0, n1a = 0, n1b = 0, n2a = 0, n2b = 0, dna = 0, dnb = 0;

    for (int ke = 0; ke <= 64; ke += 2) {
        int c = w0 + ke - 32;
        bool fast = (c >= 0) && (c <= 254);
        int ca = (c < 0) ? -c : ((c > 255) ? 510 - c : c);
        int cd = c + 1;
        int cb = (cd < 0) ? -cd : ((cd > 255) ? 510 - cd : cd);

        float Rm[10], R0[10], Rp[10], Mm[10], M0[10], Mp[10];
#pragma unroll
        for (int j = 0; j < 10; j++) {
            R0[j] = Rsm[ke * 10 + j];
            M0[j] = Msm[ke * 10 + j];
            Rp[j] = (ke < 64) ? Rsm[(ke + 1) * 10 + j] : 0.f;
            Mp[j] = (ke < 64) ? Msm[(ke + 1) * 10 + j] : 0.f;
            Rm[j] = (ke > 0) ? Rsm[(ke - 1) * 10 + j] : 0.f;
            Mm[j] = (ke > 0) ? Msm[(ke - 1) * 10 + j] : 0.f;
        }
#pragma unroll
        for (int j = 0; j < 10; j++) {
            float2 g;
#define LOADP(p) (fast ? *(const float2*)&P[(p) * 258 + c] \
                       : make_float2(P[(p) * 258 + ca], P[(p) * 258 + cb]))
            g = LOADP(j);
            n0a += R0[j] * g.x + Rp[j] * g.y;  n0b += Rm[j] * g.x + R0[j] * g.y;
            g = LOADP(10 + j);
            n1a += R0[j] * g.x + Rp[j] * g.y;  n1b += Rm[j] * g.x + R0[j] * g.y;
            g = LOADP(20 + j);
            n2a += R0[j] * g.x + Rp[j] * g.y;  n2b += Rm[j] * g.x + R0[j] * g.y;
            g = LOADP(30 + j);
            dna += R0[j] * g.x + Rp[j] * g.y;  dnb += Rm[j] * g.x + R0[j] * g.y;
            g = LOADP(40 + j);
            n0a += M0[j] * g.x + Mp[j] * g.y;  n0b += Mm[j] * g.x + M0[j] * g.y;
            g = LOADP(50 + j);
            n1a += M0[j] * g.x + Mp[j] * g.y;  n1b += Mm[j] * g.x + M0[j] * g.y;
            g = LOADP(60 + j);
            n2a += M0[j] * g.x + Mp[j] * g.y;  n2b += Mm[j] * g.x + M0[j] * g.y;
#undef LOADP
        }
    }
    float dmu = g_denmu;
    dna += dmu;
    dnb += dmu;
    size_t base = (size_t)h * 256 + w0;
    *reinterpret_cast<float2*>(&out[0 * NPIX + base]) = make_float2(n0a / dna, n0b / dnb);
    *reinterpret_cast<float2*>(&out[1 * NPIX + base]) = make_float2(n1a / dna, n1b / dnb);
    *reinterpret_cast<float2*>(&out[2 * NPIX + base]) = make_float2(n2a / dna, n2b / dnb);
}

// ---------------- launcher ----------------
extern "C" void kernel_launch(void* const* d_in, const int* in_sizes, int n_in,
                              void* d_out, int out_size) {
    const float* img  = (const float*)d_in[0];
    const float* zern = (const float*)d_in[1];
    const float* fc1w = (const float*)d_in[2];
    const float* fc1b = (const float*)d_in[3];
    const float* fc2w = (const float*)d_in[4];
    const float* fc2b = (const float*)d_in[5];
    const float* fc3w = (const float*)d_in[6];
    const float* fc3b = (const float*)d_in[7];
    const float* bl   = (const float*)d_in[8];
    const float* br   = (const float*)d_in[9];
    const float* mu   = (const float*)d_in[10];
    float* out = (float*)d_out;

    auto l1 = k_mlp<200, 33, 35, 2, 1>;
    auto l2 = k_mlp<200, 200, 200, 0, 1>;
    auto l3 = k_mlp<100, 200, 200, 0, 0>;
    // smem: NP*KS*2 copies*2B + NP*4B
    // l1: KP=48,KS=56 -> 200*56*2*2 + 800 = 45600
    // l2: KP=208,KS=216 -> 200*216*2*2 + 800 = 173600
    // l3: NP=104 -> 104*216*2*2 + 416 = 90272
    cudaFuncSetAttribute(l1, cudaFuncAttributeMaxDynamicSharedMemorySize, 45600);
    cudaFuncSetAttribute(l2, cudaFuncAttributeMaxDynamicSharedMemorySize, 173600);
    cudaFuncSetAttribute(l3, cudaFuncAttributeMaxDynamicSharedMemorySize, 90272);
    cudaFuncSetAttribute(k_vert, cudaFuncAttributeMaxDynamicSharedMemorySize, 110132);
    cudaFuncSetAttribute(k_horiz, cudaFuncAttributeMaxDynamicSharedMemorySize, 77440);

    float *h1, *h2, *coef;
    cudaGetSymbolAddress((void**)&h1, g_h1);
    cudaGetSymbolAddress((void**)&h2, g_h2);
    cudaGetSymbolAddress((void**)&coef, g_coef);

    k_denmu<<<1, 64>>>(mu);
    k_gridsample<<<256, 256>>>(img, zern);
    l1<<<148, 512, 45600>>>(zern, fc1w, fc1b, h1);
    l2<<<148, 512, 173600>>>(h1, fc2w, fc2b, h2);
    l3<<<148, 512, 90272>>>(h2, fc3w, fc3b, coef);
    k_vert<<<256, 128, 110132>>>(bl);
    k_vmu<<<256, 256>>>(mu);
    k_horiz<<<256, 128, 77440>>>(br, mu, out);
}